// round 14
// baseline (speedup 1.0000x reference)
#include <cuda_runtime.h>
#include <cstdint>

// ----------------------------------------------------------------------------
// BaseLUTLayer = multilinear polynomial eval in Moebius coefficient basis.
//   prep_kernel: (a) transpose x -> xT[IN][B] (64x64 float4 tiles)
//                (b) Moebius transform lut -> C
//   lut_fold_kernel: REGISTER-RESIDENT coefficients (c[64] per warp, loaded
//     once), grid split over both o-groups AND batch chunks (1024 blocks).
//     Each loop body processes 64 b as TWO independent 32-lane streams that
//     share the coefficient registers -> doubled ILP to cover x-load latency,
//     with next-body x prefetched. No coefficient memory stream at all.
// ----------------------------------------------------------------------------

#define B_CHUNK 256     // batch elements per block
#define N_BODY  (B_CHUNK / 64)

__device__ float g_xT[4 * 1024 * 1024];
__device__ float g_C [1 * 1024 * 1024];

// ---- fused prep: transpose (first t_blocks) + Moebius coeffs (rest) --------
__global__ __launch_bounds__(256)
void prep_kernel(const float* __restrict__ x, float* __restrict__ xT,
                 const float* __restrict__ lut, float* __restrict__ C,
                 int B, int IN, int OUT, int t_blocks, int tiles_x) {
    if ((int)blockIdx.x < t_blocks) {
        __shared__ float tile[64][65];
        const int tid = threadIdx.x;
        const int c0 = (blockIdx.x % tiles_x) * 64;    // IN base
        const int r0 = (blockIdx.x / tiles_x) * 64;    // B base
        float4 v[4];
#pragma unroll
        for (int p = 0; p < 4; p++) {
            int idx  = p * 256 + tid;
            int row  = idx >> 4;
            int col4 = idx & 15;
            int r = r0 + row, c = c0 + col4 * 4;
            v[p] = (r < B && c + 3 < IN)
                 ? *reinterpret_cast<const float4*>(&x[(size_t)r * IN + c])
                 : make_float4(0.f, 0.f, 0.f, 0.f);
        }
#pragma unroll
        for (int p = 0; p < 4; p++) {
            int idx  = p * 256 + tid;
            int row  = idx >> 4;
            int col4 = idx & 15;
            tile[row][col4 * 4 + 0] = v[p].x;
            tile[row][col4 * 4 + 1] = v[p].y;
            tile[row][col4 * 4 + 2] = v[p].z;
            tile[row][col4 * 4 + 3] = v[p].w;
        }
        __syncthreads();
#pragma unroll
        for (int p = 0; p < 4; p++) {
            int idx = p * 256 + tid;
            int inl = idx >> 4;
            int b4  = idx & 15;
            int in = c0 + inl, bb = r0 + b4 * 4;
            if (in < IN && bb + 3 < B) {
                float4 w = make_float4(tile[b4 * 4 + 0][inl],
                                       tile[b4 * 4 + 1][inl],
                                       tile[b4 * 4 + 2][inl],
                                       tile[b4 * 4 + 3][inl]);
                *reinterpret_cast<float4*>(&xT[(size_t)in * B + bb]) = w;
            }
        }
    } else {
        int o = (blockIdx.x - t_blocks) * 256 + threadIdx.x;
        if (o >= OUT) return;
        float a[64];
        const float4* src = reinterpret_cast<const float4*>(lut + (size_t)o * 64);
#pragma unroll
        for (int i = 0; i < 16; i++) {
            float4 w = __ldg(&src[i]);
            a[4 * i] = w.x; a[4 * i + 1] = w.y; a[4 * i + 2] = w.z; a[4 * i + 3] = w.w;
        }
#pragma unroll
        for (int j = 0; j < 6; j++) {
            int s = 1 << j;
#pragma unroll
            for (int k = 0; k < 64; k++)
                if (k & s) a[k] -= a[k ^ s];
        }
        float4* dst = reinterpret_cast<float4*>(C + (size_t)o * 64);
#pragma unroll
        for (int i = 0; i < 16; i++)
            dst[i] = make_float4(a[4 * i], a[4 * i + 1], a[4 * i + 2], a[4 * i + 3]);
    }
}

// ---- fold: register-resident coeffs, 2-stream bodies, B-split grid ---------
__global__ __launch_bounds__(256, 2)
void lut_fold_kernel(const float* __restrict__ xT,
                     const float* __restrict__ C,
                     const int*   __restrict__ mapping,
                     float* __restrict__ out,
                     int B, int OUT) {
    __shared__ float s_res[8][B_CHUNK + 4];

    const int lane   = threadIdx.x & 31;
    const int w      = threadIdx.x >> 5;          // warp id = o_local
    const int o0     = blockIdx.y * 8;
    const int b_base = blockIdx.x * B_CHUNK;
    int o = o0 + w;
    if (o >= OUT) o = OUT - 1;

    // one-time prologue: coefficients + mapping into registers
    float c[64];
#pragma unroll
    for (int k = 0; k < 64; k++) c[k] = __ldg(&C[(size_t)o * 64 + k]);
    int m[6];
#pragma unroll
    for (int j = 0; j < 6; j++) m[j] = __ldg(&mapping[(size_t)o * 6 + j]);

    // prefetch body 0 (two 32-lane streams)
    float xn[2][6];
#pragma unroll
    for (int s = 0; s < 2; s++) {
        int b = b_base + s * 32 + lane;
#pragma unroll
        for (int j = 0; j < 6; j++)
            xn[s][j] = (b < B) ? __ldg(&xT[(size_t)m[j] * B + b]) : 0.f;
    }

#pragma unroll
    for (int nb = 0; nb < N_BODY; nb++) {
        float xv[2][6];
#pragma unroll
        for (int s = 0; s < 2; s++)
#pragma unroll
            for (int j = 0; j < 6; j++) xv[s][j] = xn[s][j];

        if (nb + 1 < N_BODY) {                    // prefetch next body
#pragma unroll
            for (int s = 0; s < 2; s++) {
                int b = b_base + (nb + 1) * 64 + s * 32 + lane;
#pragma unroll
                for (int j = 0; j < 6; j++)
                    xn[s][j] = (b < B) ? __ldg(&xT[(size_t)m[j] * B + b]) : 0.f;
            }
        }

        // two independent scalar Horner streams sharing c[] registers
#pragma unroll
        for (int s = 0; s < 2; s++) {
            float r[8];
#pragma unroll
            for (int g = 0; g < 8; g++) {
                float v0 = fmaf(xv[s][0], c[8 * g + 1], c[8 * g + 0]);
                float v1 = fmaf(xv[s][0], c[8 * g + 3], c[8 * g + 2]);
                float v2 = fmaf(xv[s][0], c[8 * g + 5], c[8 * g + 4]);
                float v3 = fmaf(xv[s][0], c[8 * g + 7], c[8 * g + 6]);
                float u0 = fmaf(xv[s][1], v1, v0);
                float u1 = fmaf(xv[s][1], v3, v2);
                r[g] = fmaf(xv[s][2], u1, u0);
            }
            float p0 = fmaf(xv[s][3], r[1], r[0]);
            float p1 = fmaf(xv[s][3], r[3], r[2]);
            float p2 = fmaf(xv[s][3], r[5], r[4]);
            float p3 = fmaf(xv[s][3], r[7], r[6]);
            float q0 = fmaf(xv[s][4], p1, p0);
            float q1 = fmaf(xv[s][4], p3, p2);
            float res = fmaf(xv[s][5], q1, q0);

            s_res[w][nb * 64 + s * 32 + lane] = res;   // STS.32 conflict-free
        }
    }
    __syncthreads();

    // writeout: out[b][o0..o0+7] as two float4 (full 32B sectors)
    const int tid = threadIdx.x;
#pragma unroll
    for (int idx = 0; idx < B_CHUNK * 2; idx += 256) {
        int i  = idx + tid;
        int bl = i >> 1;
        int h  = i & 1;
        int b  = b_base + bl;
        int oo = o0 + h * 4;
        if (b < B && oo + 3 < OUT) {
            float4 val = make_float4(s_res[h * 4 + 0][bl],
                                     s_res[h * 4 + 1][bl],
                                     s_res[h * 4 + 2][bl],
                                     s_res[h * 4 + 3][bl]);
            *reinterpret_cast<float4*>(&out[(size_t)b * OUT + oo]) = val;
        }
    }
}

extern "C" void kernel_launch(void* const* d_in, const int* in_sizes, int n_in,
                              void* d_out, int out_size) {
    const float* x       = (const float*)d_in[0];
    const float* lut     = (const float*)d_in[1];
    const int*   mapping = (const int*)d_in[2];
    float*       out     = (float*)d_out;

    int OUT = in_sizes[2] / 6;          // mapping is (OUT, 6)
    int B   = out_size / OUT;           // out is (B, OUT)
    int IN  = in_sizes[0] / B;          // x is (B, IN)

    float* xT = nullptr;
    float* C  = nullptr;
    cudaGetSymbolAddress((void**)&xT, g_xT);
    cudaGetSymbolAddress((void**)&C,  g_C);

    int tiles_x  = (IN + 63) / 64;
    int tiles_y  = (B + 63) / 64;
    int t_blocks = tiles_x * tiles_y;
    int c_blocks = (OUT + 255) / 256;
    prep_kernel<<<t_blocks + c_blocks, 256>>>(x, xT, lut, C, B, IN, OUT, t_blocks, tiles_x);

    dim3 grd((B + B_CHUNK - 1) / B_CHUNK, (OUT + 7) / 8);
    lut_fold_kernel<<<grd, 256>>>(xT, C, mapping, out, B, OUT);
}

// round 15
// speedup vs baseline: 1.0411x; 1.0411x over previous
#include <cuda_runtime.h>
#include <cstdint>

// ----------------------------------------------------------------------------
// BaseLUTLayer = multilinear polynomial eval in Moebius coefficient basis.
//   prep_kernel: (a) transpose x -> xT[IN][B] (64x64 float4 tiles)
//                (b) Moebius transform lut -> C
//   lut_fold_kernel: REGISTER-RESIDENT coefficients (c[64] per warp, loaded
//     once), grid split over both o-groups AND batch chunks (1024 blocks).
//     Each loop body processes 64 b as TWO independent 32-lane streams that
//     share the coefficient registers -> doubled ILP to cover x-load latency,
//     with next-body x prefetched. No coefficient memory stream at all.
// ----------------------------------------------------------------------------

#define B_CHUNK 256     // batch elements per block
#define N_BODY  (B_CHUNK / 64)

__device__ float g_xT[4 * 1024 * 1024];
__device__ float g_C [1 * 1024 * 1024];

// ---- fused prep: transpose (first t_blocks) + Moebius coeffs (rest) --------
__global__ __launch_bounds__(256)
void prep_kernel(const float* __restrict__ x, float* __restrict__ xT,
                 const float* __restrict__ lut, float* __restrict__ C,
                 int B, int IN, int OUT, int t_blocks, int tiles_x) {
    if ((int)blockIdx.x < t_blocks) {
        __shared__ float tile[64][65];
        const int tid = threadIdx.x;
        const int c0 = (blockIdx.x % tiles_x) * 64;    // IN base
        const int r0 = (blockIdx.x / tiles_x) * 64;    // B base
        float4 v[4];
#pragma unroll
        for (int p = 0; p < 4; p++) {
            int idx  = p * 256 + tid;
            int row  = idx >> 4;
            int col4 = idx & 15;
            int r = r0 + row, c = c0 + col4 * 4;
            v[p] = (r < B && c + 3 < IN)
                 ? *reinterpret_cast<const float4*>(&x[(size_t)r * IN + c])
                 : make_float4(0.f, 0.f, 0.f, 0.f);
        }
#pragma unroll
        for (int p = 0; p < 4; p++) {
            int idx  = p * 256 + tid;
            int row  = idx >> 4;
            int col4 = idx & 15;
            tile[row][col4 * 4 + 0] = v[p].x;
            tile[row][col4 * 4 + 1] = v[p].y;
            tile[row][col4 * 4 + 2] = v[p].z;
            tile[row][col4 * 4 + 3] = v[p].w;
        }
        __syncthreads();
#pragma unroll
        for (int p = 0; p < 4; p++) {
            int idx = p * 256 + tid;
            int inl = idx >> 4;
            int b4  = idx & 15;
            int in = c0 + inl, bb = r0 + b4 * 4;
            if (in < IN && bb + 3 < B) {
                float4 w = make_float4(tile[b4 * 4 + 0][inl],
                                       tile[b4 * 4 + 1][inl],
                                       tile[b4 * 4 + 2][inl],
                                       tile[b4 * 4 + 3][inl]);
                *reinterpret_cast<float4*>(&xT[(size_t)in * B + bb]) = w;
            }
        }
    } else {
        int o = (blockIdx.x - t_blocks) * 256 + threadIdx.x;
        if (o >= OUT) return;
        float a[64];
        const float4* src = reinterpret_cast<const float4*>(lut + (size_t)o * 64);
#pragma unroll
        for (int i = 0; i < 16; i++) {
            float4 w = __ldg(&src[i]);
            a[4 * i] = w.x; a[4 * i + 1] = w.y; a[4 * i + 2] = w.z; a[4 * i + 3] = w.w;
        }
#pragma unroll
        for (int j = 0; j < 6; j++) {
            int s = 1 << j;
#pragma unroll
            for (int k = 0; k < 64; k++)
                if (k & s) a[k] -= a[k ^ s];
        }
        float4* dst = reinterpret_cast<float4*>(C + (size_t)o * 64);
#pragma unroll
        for (int i = 0; i < 16; i++)
            dst[i] = make_float4(a[4 * i], a[4 * i + 1], a[4 * i + 2], a[4 * i + 3]);
    }
}

// ---- fold: register-resident coeffs, 2-stream bodies, B-split grid ---------
__global__ __launch_bounds__(256, 2)
void lut_fold_kernel(const float* __restrict__ xT,
                     const float* __restrict__ C,
                     const int*   __restrict__ mapping,
                     float* __restrict__ out,
                     int B, int OUT) {
    __shared__ float s_res[8][B_CHUNK + 4];

    const int lane   = threadIdx.x & 31;
    const int w      = threadIdx.x >> 5;          // warp id = o_local
    const int o0     = blockIdx.y * 8;
    const int b_base = blockIdx.x * B_CHUNK;
    int o = o0 + w;
    if (o >= OUT) o = OUT - 1;

    // one-time prologue: coefficients + mapping into registers
    float c[64];
#pragma unroll
    for (int k = 0; k < 64; k++) c[k] = __ldg(&C[(size_t)o * 64 + k]);
    int m[6];
#pragma unroll
    for (int j = 0; j < 6; j++) m[j] = __ldg(&mapping[(size_t)o * 6 + j]);

    // prefetch body 0 (two 32-lane streams)
    float xn[2][6];
#pragma unroll
    for (int s = 0; s < 2; s++) {
        int b = b_base + s * 32 + lane;
#pragma unroll
        for (int j = 0; j < 6; j++)
            xn[s][j] = (b < B) ? __ldg(&xT[(size_t)m[j] * B + b]) : 0.f;
    }

#pragma unroll
    for (int nb = 0; nb < N_BODY; nb++) {
        float xv[2][6];
#pragma unroll
        for (int s = 0; s < 2; s++)
#pragma unroll
            for (int j = 0; j < 6; j++) xv[s][j] = xn[s][j];

        if (nb + 1 < N_BODY) {                    // prefetch next body
#pragma unroll
            for (int s = 0; s < 2; s++) {
                int b = b_base + (nb + 1) * 64 + s * 32 + lane;
#pragma unroll
                for (int j = 0; j < 6; j++)
                    xn[s][j] = (b < B) ? __ldg(&xT[(size_t)m[j] * B + b]) : 0.f;
            }
        }

        // two independent scalar Horner streams sharing c[] registers
#pragma unroll
        for (int s = 0; s < 2; s++) {
            float r[8];
#pragma unroll
            for (int g = 0; g < 8; g++) {
                float v0 = fmaf(xv[s][0], c[8 * g + 1], c[8 * g + 0]);
                float v1 = fmaf(xv[s][0], c[8 * g + 3], c[8 * g + 2]);
                float v2 = fmaf(xv[s][0], c[8 * g + 5], c[8 * g + 4]);
                float v3 = fmaf(xv[s][0], c[8 * g + 7], c[8 * g + 6]);
                float u0 = fmaf(xv[s][1], v1, v0);
                float u1 = fmaf(xv[s][1], v3, v2);
                r[g] = fmaf(xv[s][2], u1, u0);
            }
            float p0 = fmaf(xv[s][3], r[1], r[0]);
            float p1 = fmaf(xv[s][3], r[3], r[2]);
            float p2 = fmaf(xv[s][3], r[5], r[4]);
            float p3 = fmaf(xv[s][3], r[7], r[6]);
            float q0 = fmaf(xv[s][4], p1, p0);
            float q1 = fmaf(xv[s][4], p3, p2);
            float res = fmaf(xv[s][5], q1, q0);

            s_res[w][nb * 64 + s * 32 + lane] = res;   // STS.32 conflict-free
        }
    }
    __syncthreads();

    // writeout: out[b][o0..o0+7] as two float4 (full 32B sectors)
    const int tid = threadIdx.x;
#pragma unroll
    for (int idx = 0; idx < B_CHUNK * 2; idx += 256) {
        int i  = idx + tid;
        int bl = i >> 1;
        int h  = i & 1;
        int b  = b_base + bl;
        int oo = o0 + h * 4;
        if (b < B && oo + 3 < OUT) {
            float4 val = make_float4(s_res[h * 4 + 0][bl],
                                     s_res[h * 4 + 1][bl],
                                     s_res[h * 4 + 2][bl],
                                     s_res[h * 4 + 3][bl]);
            *reinterpret_cast<float4*>(&out[(size_t)b * OUT + oo]) = val;
        }
    }
}

extern "C" void kernel_launch(void* const* d_in, const int* in_sizes, int n_in,
                              void* d_out, int out_size) {
    const float* x       = (const float*)d_in[0];
    const float* lut     = (const float*)d_in[1];
    const int*   mapping = (const int*)d_in[2];
    float*       out     = (float*)d_out;

    int OUT = in_sizes[2] / 6;          // mapping is (OUT, 6)
    int B   = out_size / OUT;           // out is (B, OUT)
    int IN  = in_sizes[0] / B;          // x is (B, IN)

    float* xT = nullptr;
    float* C  = nullptr;
    cudaGetSymbolAddress((void**)&xT, g_xT);
    cudaGetSymbolAddress((void**)&C,  g_C);

    int tiles_x  = (IN + 63) / 64;
    int tiles_y  = (B + 63) / 64;
    int t_blocks = tiles_x * tiles_y;
    int c_blocks = (OUT + 255) / 256;
    prep_kernel<<<t_blocks + c_blocks, 256>>>(x, xT, lut, C, B, IN, OUT, t_blocks, tiles_x);

    dim3 grd((B + B_CHUNK - 1) / B_CHUNK, (OUT + 7) / 8);
    lut_fold_kernel<<<grd, 256>>>(xT, C, mapping, out, B, OUT);
}

// round 16
// speedup vs baseline: 1.3947x; 1.3397x over previous
#include <cuda_runtime.h>
#include <cstdint>

// ----------------------------------------------------------------------------
// BaseLUTLayer = multilinear polynomial eval in Moebius coefficient basis.
//   prep_kernel: transpose x -> xT[IN][B] ONLY (64x64 float4 tiles, no tail).
//   lut_fold_kernel: computes its own Moebius coefficients in-warp via
//     shfl-xor butterflies (lane owns lut entries 2*lane, 2*lane+1; bit0 is
//     intra-lane, bits1-5 are warp butterflies), stores duplicated f32x2
//     pairs to smem once, then the validated nested-Horner f32x2 fold
//     (BPT=4: each thread evaluates 4 batch elems as two f32x2 sets).
// ----------------------------------------------------------------------------

#define O_TILE 8
#define BPT    4
#define B_TILE (32 * BPT)   // 128

__device__ float g_xT[4 * 1024 * 1024];   // transposed x scratch

static __device__ __forceinline__ unsigned long long pack2(float lo, float hi) {
    unsigned long long r;
    asm("mov.b64 %0, {%1, %2};" : "=l"(r) : "f"(lo), "f"(hi));
    return r;
}
static __device__ __forceinline__ void unpack2(unsigned long long v, float& lo, float& hi) {
    asm("mov.b64 {%0, %1}, %2;" : "=f"(lo), "=f"(hi) : "l"(v));
}
static __device__ __forceinline__ unsigned long long fma2(unsigned long long a,
                                                          unsigned long long b,
                                                          unsigned long long c) {
    unsigned long long d;
    asm("fma.rn.f32x2 %0, %1, %2, %3;" : "=l"(d) : "l"(a), "l"(b), "l"(c));
    return d;
}

// ---- prep: transpose only ---------------------------------------------------
__global__ __launch_bounds__(256)
void prep_kernel(const float* __restrict__ x, float* __restrict__ xT,
                 int B, int IN, int tiles_x) {
    __shared__ float tile[64][65];
    const int tid = threadIdx.x;
    const int c0 = (blockIdx.x % tiles_x) * 64;    // IN base
    const int r0 = (blockIdx.x / tiles_x) * 64;    // B base
    float4 v[4];
#pragma unroll
    for (int p = 0; p < 4; p++) {
        int idx  = p * 256 + tid;
        int row  = idx >> 4;
        int col4 = idx & 15;
        int r = r0 + row, c = c0 + col4 * 4;
        v[p] = (r < B && c + 3 < IN)
             ? *reinterpret_cast<const float4*>(&x[(size_t)r * IN + c])
             : make_float4(0.f, 0.f, 0.f, 0.f);
    }
#pragma unroll
    for (int p = 0; p < 4; p++) {
        int idx  = p * 256 + tid;
        int row  = idx >> 4;
        int col4 = idx & 15;
        tile[row][col4 * 4 + 0] = v[p].x;
        tile[row][col4 * 4 + 1] = v[p].y;
        tile[row][col4 * 4 + 2] = v[p].z;
        tile[row][col4 * 4 + 3] = v[p].w;
    }
    __syncthreads();
#pragma unroll
    for (int p = 0; p < 4; p++) {
        int idx = p * 256 + tid;
        int inl = idx >> 4;
        int b4  = idx & 15;
        int in = c0 + inl, bb = r0 + b4 * 4;
        if (in < IN && bb + 3 < B) {
            float4 w = make_float4(tile[b4 * 4 + 0][inl],
                                   tile[b4 * 4 + 1][inl],
                                   tile[b4 * 4 + 2][inl],
                                   tile[b4 * 4 + 3][inl]);
            *reinterpret_cast<float4*>(&xT[(size_t)in * B + bb]) = w;
        }
    }
}

// ---- fold: in-warp Moebius + smem f32x2 nested Horner, BPT=4 ----------------
__global__ __launch_bounds__(32 * O_TILE)
void lut_fold_kernel(const float* __restrict__ xT,
                     const float* __restrict__ lut_table,
                     const int*   __restrict__ mapping,
                     float* __restrict__ out,
                     int B, int OUT) {
    __shared__ ulonglong2 s_lut[O_TILE][32];
    __shared__ float      s_res[O_TILE][B_TILE + 4];

    const int lane = threadIdx.x;
    const int ty   = threadIdx.y;
    const int tid  = ty * 32 + lane;
    const int b0   = blockIdx.x * B_TILE;
    const int o0   = blockIdx.y * O_TILE;
    int o = o0 + ty;
    if (o >= OUT) o = OUT - 1;

    // ---- in-warp Moebius transform: lane owns entries (2*lane, 2*lane+1) ---
    float2 eu = __ldg(reinterpret_cast<const float2*>(&lut_table[(size_t)o * 64 + 2 * lane]));
    float e0 = eu.x, e1 = eu.y;
    e1 -= e0;                                           // bit 0 (intra-lane)
#pragma unroll
    for (int j = 0; j < 5; j++) {                       // bits 1..5 (butterflies)
        int s = 1 << j;
        float p0 = __shfl_xor_sync(0xffffffffu, e0, s);
        float p1 = __shfl_xor_sync(0xffffffffu, e1, s);
        if (lane & s) { e0 -= p0; e1 -= p1; }
    }

    // per-warp mapping row (uniform across lanes)
    int m[6];
#pragma unroll
    for (int j = 0; j < 6; j++) m[j] = __ldg(&mapping[(size_t)o * 6 + j]);

    // x loads: one LDG.128 per bit = both f32x2 sets (issued before smem fill)
    const int bq = b0 + lane * BPT;
    const bool vb = (bq + BPT - 1 < B);
    unsigned long long Xa[6], Xb[6];
#pragma unroll
    for (int j = 0; j < 6; j++) {
        if (vb) {
            ulonglong2 xv = *reinterpret_cast<const ulonglong2*>(&xT[(size_t)m[j] * B + bq]);
            Xa[j] = xv.x;
            Xb[j] = xv.y;
        } else {
            Xa[j] = 0ull; Xb[j] = 0ull;
        }
    }

    // duplicated coefficient pairs -> smem (per-warp row, warp-sync only)
    {
        ulonglong2 e;
        e.x = pack2(e0, e0);
        e.y = pack2(e1, e1);
        s_lut[ty][lane] = e;
    }
    __syncwarp();

    const ulonglong2* lrow = &s_lut[ty][0];

    unsigned long long ra[4], rb[4];
#pragma unroll
    for (int g = 0; g < 4; g++) {
        unsigned long long va[8], vbv[8];
#pragma unroll
        for (int i = 0; i < 8; i++) {
            ulonglong2 e = lrow[g * 8 + i];             // LDS.128 warp-broadcast
            va[i]  = fma2(Xa[0], e.y, e.x);             // bit 0
            vbv[i] = fma2(Xb[0], e.y, e.x);
        }
#pragma unroll
        for (int i = 0; i < 4; i++) {                   // bit 1
            va[i]  = fma2(Xa[1], va[2 * i + 1],  va[2 * i]);
            vbv[i] = fma2(Xb[1], vbv[2 * i + 1], vbv[2 * i]);
        }
#pragma unroll
        for (int i = 0; i < 2; i++) {                   // bit 2
            va[i]  = fma2(Xa[2], va[2 * i + 1],  va[2 * i]);
            vbv[i] = fma2(Xb[2], vbv[2 * i + 1], vbv[2 * i]);
        }
        ra[g] = fma2(Xa[3], va[1],  va[0]);             // bit 3
        rb[g] = fma2(Xb[3], vbv[1], vbv[0]);
    }
    unsigned long long sa0 = fma2(Xa[4], ra[1], ra[0]);     // bit 4
    unsigned long long sa1 = fma2(Xa[4], ra[3], ra[2]);
    unsigned long long sb0 = fma2(Xb[4], rb[1], rb[0]);
    unsigned long long sb1 = fma2(Xb[4], rb[3], rb[2]);
    unsigned long long resa = fma2(Xa[5], sa1, sa0);        // bit 5
    unsigned long long resb = fma2(Xb[5], sb1, sb0);

    float r0f, r1f, r2f, r3f;
    unpack2(resa, r0f, r1f);
    unpack2(resb, r2f, r3f);
    *reinterpret_cast<float4*>(&s_res[ty][lane * BPT]) = make_float4(r0f, r1f, r2f, r3f);
    __syncthreads();

    // writeout: o fastest, float4 stores (full 32B sectors)
    int bw   = tid >> 1;          // 0..127
    int half = tid & 1;
    int oo   = o0 + half * 4;
    int bg   = b0 + bw;
    if (bg < B && oo + 3 < OUT) {
        float4 val = make_float4(s_res[half * 4 + 0][bw],
                                 s_res[half * 4 + 1][bw],
                                 s_res[half * 4 + 2][bw],
                                 s_res[half * 4 + 3][bw]);
        *reinterpret_cast<float4*>(&out[(size_t)bg * OUT + oo]) = val;
    }
}

extern "C" void kernel_launch(void* const* d_in, const int* in_sizes, int n_in,
                              void* d_out, int out_size) {
    const float* x       = (const float*)d_in[0];
    const float* lut     = (const float*)d_in[1];
    const int*   mapping = (const int*)d_in[2];
    float*       out     = (float*)d_out;

    int OUT = in_sizes[2] / 6;          // mapping is (OUT, 6)
    int B   = out_size / OUT;           // out is (B, OUT)
    int IN  = in_sizes[0] / B;          // x is (B, IN)

    float* xT = nullptr;
    cudaGetSymbolAddress((void**)&xT, g_xT);

    int tiles_x = (IN + 63) / 64;
    int tiles_y = (B + 63) / 64;
    prep_kernel<<<tiles_x * tiles_y, 256>>>(x, xT, B, IN, tiles_x);

    dim3 blk(32, O_TILE);
    dim3 grd((B + B_TILE - 1) / B_TILE, (OUT + O_TILE - 1) / O_TILE);
    lut_fold_kernel<<<grd, blk>>>(xT, lut, mapping, out, B, OUT);
}